// round 11
// baseline (speedup 1.0000x reference)
#include <cuda_runtime.h>

#define NMAX 50000
#define EMAX 800000
#define HDIM 128
#define GNUM 256
#define ODIM 10
#define BN_EPS 1e-5f

// ---------------- scratch: device globals ----------------
__device__ __align__(16) float g_h  [NMAX * HDIM];   // GEMM output features
__device__ __align__(16) float g_agg[NMAX * HDIM];   // aggregation output
__device__ int   g_degi[NMAX];
__device__ int   g_row [NMAX + 1];
__device__ int   g_cur [NMAX];
__device__ int   g_col [EMAX];
__device__ float g_dis [NMAX];
__device__ float g_stats[512];                        // sum | sumsq | scale | shift
__device__ __align__(16) float g_pool[GNUM * HDIM];
__device__ float g_cnt [GNUM];

// ---------------- init: zero degi + pool + cnt ----------------
__global__ void k_init(int n) {
    int i = blockIdx.x * blockDim.x + threadIdx.x;
    if (i < n) g_degi[i] = 0;
    if (i < GNUM * HDIM) g_pool[i] = 0.f;
    if (i < GNUM) g_cnt[i] = 0.f;
}

__global__ void k_deg_count(const int* __restrict__ dst, int E) {
    int e = blockIdx.x * blockDim.x + threadIdx.x;
    if (e < E) atomicAdd(&g_degi[dst[e]], 1);
}

// single block, 1024 threads: exclusive scan of degi -> row; also dis + cur
__global__ void k_scan(int n) {
    __shared__ int sdata[1024];
    const int t = threadIdx.x;
    const int chunk = (n + 1023) >> 10;
    int beg = t * chunk;
    int end = min(n, beg + chunk);
    if (beg > end) beg = end;
    int s = 0;
    for (int i = beg; i < end; i++) s += g_degi[i];
    sdata[t] = s;
    __syncthreads();
    for (int off = 1; off < 1024; off <<= 1) {
        int v = (t >= off) ? sdata[t - off] : 0;
        __syncthreads();
        sdata[t] += v;
        __syncthreads();
    }
    int run = t ? sdata[t - 1] : 0;
    for (int i = beg; i < end; i++) {
        int d = g_degi[i];
        g_row[i] = run;
        g_cur[i] = run;
        g_dis[i] = rsqrtf((float)(d + 1));
        run += d;
    }
    if (end == n) g_row[n] = run;
}

__global__ void k_fill(const int* __restrict__ src, const int* __restrict__ dst, int E) {
    int e = blockIdx.x * blockDim.x + threadIdx.x;
    if (e < E) {
        int d = dst[e];
        int p = atomicAdd(&g_cur[d], 1);
        g_col[p] = src[e];
    }
}

// ---------------- GEMM: g_h = A @ W ----------------
// APPLY_BN=false: A = Aext (layer 1 input x)
// APPLY_BN=true : A = relu(g_agg * scale + shift), scale/shift in g_stats[256..512)
// Block 0 additionally zeroes g_stats[0..256) for the *next* gather's stats.
template <bool APPLY_BN>
__global__ void k_gemm(const float* __restrict__ Aext, const float* __restrict__ W, int n) {
    __shared__ float sW[32][128];   // 16 KB
    __shared__ float sA[64][33];    // pad 33
    const int t = threadIdx.x;       // 256 threads
    const int row0 = blockIdx.x * 64;
    const int tx = t & 15;
    const int ty = t >> 4;

    if (blockIdx.x == 0) g_stats[t] = 0.f;   // t<256 covers sum+sumsq slots

    const float* A = APPLY_BN ? (const float*)g_agg : Aext;

    float acc[4][8];
    #pragma unroll
    for (int r = 0; r < 4; r++)
        #pragma unroll
        for (int c = 0; c < 8; c++) acc[r][c] = 0.f;

    for (int kc = 0; kc < 4; kc++) {
        const int k0 = kc * 32;
        const float4* W4 = (const float4*)(W + k0 * 128);
        float4* sW4 = (float4*)&sW[0][0];
        #pragma unroll
        for (int i = t; i < 1024; i += 256) sW4[i] = W4[i];
        #pragma unroll
        for (int i = t; i < 512; i += 256) {
            int r = i >> 3, c4 = i & 7;
            int gr = row0 + r;
            int col = k0 + c4 * 4;
            float4 v = make_float4(0.f, 0.f, 0.f, 0.f);
            if (gr < n) {
                v = *(const float4*)(A + gr * 128 + col);
                if (APPLY_BN) {
                    v.x = fmaxf(fmaf(v.x, g_stats[256 + col + 0], g_stats[384 + col + 0]), 0.f);
                    v.y = fmaxf(fmaf(v.y, g_stats[256 + col + 1], g_stats[384 + col + 1]), 0.f);
                    v.z = fmaxf(fmaf(v.z, g_stats[256 + col + 2], g_stats[384 + col + 2]), 0.f);
                    v.w = fmaxf(fmaf(v.w, g_stats[256 + col + 3], g_stats[384 + col + 3]), 0.f);
                }
            }
            sA[r][c4 * 4 + 0] = v.x; sA[r][c4 * 4 + 1] = v.y;
            sA[r][c4 * 4 + 2] = v.z; sA[r][c4 * 4 + 3] = v.w;
        }
        __syncthreads();

        #pragma unroll
        for (int k = 0; k < 32; k++) {
            float4 w0 = *(const float4*)&sW[k][tx * 8];
            float4 w1 = *(const float4*)&sW[k][tx * 8 + 4];
            float ar[4];
            #pragma unroll
            for (int r = 0; r < 4; r++) ar[r] = sA[ty * 4 + r][k];
            float wc[8] = {w0.x, w0.y, w0.z, w0.w, w1.x, w1.y, w1.z, w1.w};
            #pragma unroll
            for (int r = 0; r < 4; r++)
                #pragma unroll
                for (int c = 0; c < 8; c++) acc[r][c] += ar[r] * wc[c];
        }
        __syncthreads();
    }

    #pragma unroll
    for (int r = 0; r < 4; r++) {
        int gr = row0 + ty * 4 + r;
        if (gr < n) {
            *(float4*)&g_h[gr * 128 + tx * 8]     = make_float4(acc[r][0], acc[r][1], acc[r][2], acc[r][3]);
            *(float4*)&g_h[gr * 128 + tx * 8 + 4] = make_float4(acc[r][4], acc[r][5], acc[r][6], acc[r][7]);
        }
    }
}

// ---------------- aggregation + fused BN stats ----------------
// warp per dst node: g_agg[d] = g_h[d]*dis[d]^2 + sum_e g_h[src]*dis[src]*dis[d]
// Block reduces its 8 nodes' columnwise sum/sumsq and atomically adds to g_stats[0..256).
__global__ void k_agg_gather(int n) {
    __shared__ float s_val[8][128];
    __shared__ float s_sq [8][128];
    const int warp = threadIdx.x >> 5;
    const int lane = threadIdx.x & 31;
    const int node = blockIdx.x * 8 + warp;

    float4 acc = make_float4(0.f, 0.f, 0.f, 0.f);
    if (node < n) {
        const float dd = g_dis[node];
        acc = *(const float4*)&g_h[node * 128 + (lane << 2)];
        float dd2 = dd * dd;
        acc.x *= dd2; acc.y *= dd2; acc.z *= dd2; acc.w *= dd2;

        const int beg = g_row[node];
        const int end = g_row[node + 1];
        for (int base = beg; base < end; base += 32) {
            int idx = base + lane;
            int s = 0; float ns = 0.f;
            if (idx < end) {
                s = g_col[idx];
                ns = g_dis[s] * dd;
            }
            int cnt = min(32, end - base);
            #pragma unroll 4
            for (int k = 0; k < cnt; k++) {
                int   sk = __shfl_sync(0xffffffffu, s, k);
                float nk = __shfl_sync(0xffffffffu, ns, k);
                float4 v = *(const float4*)&g_h[sk * 128 + (lane << 2)];
                acc.x += v.x * nk; acc.y += v.y * nk;
                acc.z += v.z * nk; acc.w += v.w * nk;
            }
        }
        *(float4*)&g_agg[node * 128 + (lane << 2)] = acc;
    }

    // stage per-node values + squares for the block-level stats reduction
    *(float4*)&s_val[warp][lane << 2] = acc;
    *(float4*)&s_sq [warp][lane << 2] =
        make_float4(acc.x * acc.x, acc.y * acc.y, acc.z * acc.z, acc.w * acc.w);
    __syncthreads();

    // 256 threads: half 0 sums s_val, half 1 sums s_sq, one column each
    const int c    = threadIdx.x & 127;
    const int half = threadIdx.x >> 7;
    float tot = 0.f;
    #pragma unroll
    for (int w = 0; w < 8; w++) tot += half ? s_sq[w][c] : s_val[w][c];
    atomicAdd(&g_stats[half * 128 + c], tot);
}

__global__ void k_finalize_stats(const float* __restrict__ gma, const float* __restrict__ bet, int n) {
    int c = threadIdx.x;   // 128
    float inv_n = 1.0f / (float)n;
    float mu  = g_stats[c] * inv_n;
    float var = g_stats[128 + c] * inv_n - mu * mu;
    float scale = gma[c] * rsqrtf(var + BN_EPS);
    g_stats[256 + c] = scale;
    g_stats[384 + c] = bet[c] - mu * scale;
}

// ---------------- pooling with fused layer-2 BN+ReLU (batch sorted) ----------------
__global__ void k_pool(const int* __restrict__ batch, int n) {
    const int c = threadIdx.x;   // 128 cols
    const float scale = g_stats[256 + c];
    const float shift = g_stats[384 + c];
    const int chunk = (n + gridDim.x - 1) / gridDim.x;
    const int i0 = blockIdx.x * chunk;
    const int i1 = min(n, i0 + chunk);
    if (i0 >= i1) return;

    int curg = batch[i0];
    float acc = 0.f, cacc = 0.f;
    for (int i = i0; i < i1; i++) {
        int g = batch[i];
        if (g != curg) {
            atomicAdd(&g_pool[curg * 128 + c], acc);
            if (c == 0) atomicAdd(&g_cnt[curg], cacc);
            acc = 0.f; cacc = 0.f; curg = g;
        }
        acc += fmaxf(fmaf(g_agg[i * 128 + c], scale, shift), 0.f);
        cacc += 1.f;
    }
    atomicAdd(&g_pool[curg * 128 + c], acc);
    if (c == 0) atomicAdd(&g_cnt[curg], cacc);
}

// block per graph: out[g] = (pool[g]/max(cnt,1)) @ Wout + bout
__global__ void k_out(const float* __restrict__ Wout, const float* __restrict__ bout,
                      float* __restrict__ out) {
    __shared__ float p[128];
    int g = blockIdx.x;
    float c = fmaxf(g_cnt[g], 1.0f);
    p[threadIdx.x] = g_pool[g * 128 + threadIdx.x] / c;
    __syncthreads();
    if (threadIdx.x < ODIM) {
        float s = bout[threadIdx.x];
        #pragma unroll 16
        for (int f = 0; f < 128; f++) s += p[f] * Wout[f * ODIM + threadIdx.x];
        out[g * ODIM + threadIdx.x] = s;
    }
}

// ---------------- launch ----------------
extern "C" void kernel_launch(void* const* d_in, const int* in_sizes, int n_in,
                              void* d_out, int out_size) {
    const float* x     = (const float*)d_in[0];
    const int*   ei    = (const int*)d_in[1];     // int32 (JAX default int)
    const int*   batch = (const int*)d_in[2];
    const float* W1    = (const float*)d_in[3];
    // d_in[4] = b1: cancels in training-mode BatchNorm
    const float* g1    = (const float*)d_in[5];
    const float* be1   = (const float*)d_in[6];
    const float* W2    = (const float*)d_in[7];
    // d_in[8] = b2: cancels
    const float* g2    = (const float*)d_in[9];
    const float* be2   = (const float*)d_in[10];
    const float* Wout  = (const float*)d_in[11];
    const float* bout  = (const float*)d_in[12];
    float*       out   = (float*)d_out;

    const int n = in_sizes[0] / HDIM;
    const int E = in_sizes[1] / 2;
    const int* src = ei;
    const int* dst = ei + E;

    const int TB = 256;
    const int initBlocks     = (max(n, GNUM * HDIM) + TB - 1) / TB;
    const int edgeBlocks     = (E + TB - 1) / TB;
    const int nodeWarpBlocks = (n + 7) / 8;
    const int gemmBlocks     = (n + 63) / 64;

    // --- CSR build + normalization ---
    k_init<<<initBlocks, TB>>>(n);
    k_deg_count<<<edgeBlocks, TB>>>(dst, E);
    k_scan<<<1, 1024>>>(n);
    k_fill<<<edgeBlocks, TB>>>(src, dst, E);

    // --- layer 1 ---
    k_gemm<false><<<gemmBlocks, TB>>>(x, W1, n);      // also zeroes stats[0:256)
    k_agg_gather<<<nodeWarpBlocks, TB>>>(n);          // agg + stats accumulation
    k_finalize_stats<<<1, 128>>>(g1, be1, n);

    // --- layer 2 (BN1+ReLU fused into A-load) ---
    k_gemm<true><<<gemmBlocks, TB>>>(nullptr, W2, n); // also zeroes stats[0:256)
    k_agg_gather<<<nodeWarpBlocks, TB>>>(n);
    k_finalize_stats<<<1, 128>>>(g2, be2, n);

    // --- pooling (BN2+ReLU fused) + output ---
    k_pool<<<256, 128>>>(batch, n);
    k_out<<<GNUM, 128>>>(Wout, bout, out);
}

// round 12
// speedup vs baseline: 1.2742x; 1.2742x over previous
#include <cuda_runtime.h>

#define NMAX 50000
#define EMAX 800000
#define HDIM 128
#define GNUM 256
#define ODIM 10
#define BN_EPS 1e-5f

// ---------------- scratch: device globals (zero-initialized at module load) ----------------
__device__ __align__(16) float g_h  [NMAX * HDIM];   // GEMM output features
__device__ __align__(16) float g_agg[NMAX * HDIM];   // aggregation output
__device__ int   g_degi[NMAX];                        // ZERO at entry (tail-zeroed each call)
__device__ int   g_row [NMAX + 1];
__device__ int   g_cur [NMAX];
__device__ int   g_col [EMAX];
__device__ float g_dis [NMAX];
__device__ float g_sum1[HDIM], g_sq1[HDIM];           // layer-1 BN raw stats
__device__ float g_sum2[HDIM], g_sq2[HDIM];           // layer-2 BN raw stats
__device__ __align__(16) float g_pool[GNUM * HDIM];   // ZERO at entry (tail-zeroed)
__device__ float g_cnt [GNUM];                        // ZERO at entry (tail-zeroed)

// ---------------- CSR build ----------------
__global__ void k_deg_count(const int* __restrict__ dst, int E) {
    int e = blockIdx.x * blockDim.x + threadIdx.x;
    if (e < E) atomicAdd(&g_degi[dst[e]], 1);
}

// single block, 1024 threads: coalesced tiled exclusive scan of degi -> row (+cur, dis)
__global__ void k_scan(int n) {
    __shared__ int warpsum[32];
    __shared__ int s_base;
    const int t = threadIdx.x;
    const int lane = t & 31;
    const int wid = t >> 5;
    if (t == 0) s_base = 0;
    __syncthreads();

    for (int t0 = 0; t0 < n; t0 += 1024) {
        int i = t0 + t;
        int d = (i < n) ? g_degi[i] : 0;
        // inclusive warp scan
        int v = d;
        #pragma unroll
        for (int off = 1; off < 32; off <<= 1) {
            int u = __shfl_up_sync(0xffffffffu, v, off);
            if (lane >= off) v += u;
        }
        if (lane == 31) warpsum[wid] = v;
        __syncthreads();
        if (wid == 0) {
            int w = warpsum[lane];
            #pragma unroll
            for (int off = 1; off < 32; off <<= 1) {
                int u = __shfl_up_sync(0xffffffffu, w, off);
                if (lane >= off) w += u;
            }
            warpsum[lane] = w;
        }
        __syncthreads();
        int base = s_base + (wid ? warpsum[wid - 1] : 0);
        int excl = base + v - d;
        if (i < n) {
            g_row[i] = excl;
            g_cur[i] = excl;
            g_dis[i] = rsqrtf((float)(d + 1));
        }
        __syncthreads();                       // all reads of s_base/warpsum done
        if (t == 0) s_base += warpsum[31];
        __syncthreads();
    }
    if (t == 0) g_row[n] = s_base;
}

// ---------------- GEMM body: g_h = A @ W (256 threads, 64-row tile) ----------------
// APPLY_BN: A-elements get relu(a*scale+shift) with scale/shift computed per-block
// from layer-1 raw stats (g_sum1/g_sq1) + gamma/beta.
template <bool APPLY_BN>
__device__ __forceinline__ void gemm_body(const float* __restrict__ A, const float* __restrict__ W,
                                          int n, int blk,
                                          const float* __restrict__ gma, const float* __restrict__ bet) {
    __shared__ float sW[32][128];
    __shared__ float sA[64][33];
    __shared__ float s_scale[128], s_shift[128];
    const int t = threadIdx.x;       // 256
    const int row0 = blk * 64;
    const int tx = t & 15;
    const int ty = t >> 4;

    if (APPLY_BN) {
        if (t < 128) {
            float inv_n = 1.0f / (float)n;
            float mu  = g_sum1[t] * inv_n;
            float var = g_sq1[t] * inv_n - mu * mu;
            float sc  = gma[t] * rsqrtf(var + BN_EPS);
            s_scale[t] = sc;
            s_shift[t] = bet[t] - mu * sc;
        }
        __syncthreads();
    }

    float acc[4][8];
    #pragma unroll
    for (int r = 0; r < 4; r++)
        #pragma unroll
        for (int c = 0; c < 8; c++) acc[r][c] = 0.f;

    for (int kc = 0; kc < 4; kc++) {
        const int k0 = kc * 32;
        const float4* W4 = (const float4*)(W + k0 * 128);
        float4* sW4 = (float4*)&sW[0][0];
        #pragma unroll
        for (int i = t; i < 1024; i += 256) sW4[i] = W4[i];
        #pragma unroll
        for (int i = t; i < 512; i += 256) {
            int r = i >> 3, c4 = i & 7;
            int gr = row0 + r;
            int col = k0 + c4 * 4;
            float4 v = make_float4(0.f, 0.f, 0.f, 0.f);
            if (gr < n) {
                v = *(const float4*)(A + gr * 128 + col);
                if (APPLY_BN) {
                    v.x = fmaxf(fmaf(v.x, s_scale[col + 0], s_shift[col + 0]), 0.f);
                    v.y = fmaxf(fmaf(v.y, s_scale[col + 1], s_shift[col + 1]), 0.f);
                    v.z = fmaxf(fmaf(v.z, s_scale[col + 2], s_shift[col + 2]), 0.f);
                    v.w = fmaxf(fmaf(v.w, s_scale[col + 3], s_shift[col + 3]), 0.f);
                }
            }
            sA[r][c4 * 4 + 0] = v.x; sA[r][c4 * 4 + 1] = v.y;
            sA[r][c4 * 4 + 2] = v.z; sA[r][c4 * 4 + 3] = v.w;
        }
        __syncthreads();

        #pragma unroll
        for (int k = 0; k < 32; k++) {
            float4 w0 = *(const float4*)&sW[k][tx * 8];
            float4 w1 = *(const float4*)&sW[k][tx * 8 + 4];
            float ar[4];
            #pragma unroll
            for (int r = 0; r < 4; r++) ar[r] = sA[ty * 4 + r][k];
            float wc[8] = {w0.x, w0.y, w0.z, w0.w, w1.x, w1.y, w1.z, w1.w};
            #pragma unroll
            for (int r = 0; r < 4; r++)
                #pragma unroll
                for (int c = 0; c < 8; c++) acc[r][c] += ar[r] * wc[c];
        }
        __syncthreads();
    }

    #pragma unroll
    for (int r = 0; r < 4; r++) {
        int gr = row0 + ty * 4 + r;
        if (gr < n) {
            *(float4*)&g_h[gr * 128 + tx * 8]     = make_float4(acc[r][0], acc[r][1], acc[r][2], acc[r][3]);
            *(float4*)&g_h[gr * 128 + tx * 8 + 4] = make_float4(acc[r][4], acc[r][5], acc[r][6], acc[r][7]);
        }
    }
}

// ---------------- fused layer-1 GEMM + CSR fill (independent work, one launch) ----------------
__global__ void k_l1(const float* __restrict__ x, const float* __restrict__ W1,
                     const int* __restrict__ src, const int* __restrict__ dst,
                     int n, int E, int gemmBlocks) {
    if ((int)blockIdx.x < gemmBlocks) {
        if (blockIdx.x == 0 && threadIdx.x < 128) {   // zero BOTH layers' stats before any gather
            g_sum1[threadIdx.x] = 0.f; g_sq1[threadIdx.x] = 0.f;
            g_sum2[threadIdx.x] = 0.f; g_sq2[threadIdx.x] = 0.f;
        }
        gemm_body<false>(x, W1, n, blockIdx.x, nullptr, nullptr);
    } else {
        int e = ((int)blockIdx.x - gemmBlocks) * (int)blockDim.x + (int)threadIdx.x;
        if (e < E) {
            int d = dst[e];
            int p = atomicAdd(&g_cur[d], 1);
            g_col[p] = src[e];
        }
    }
}

__global__ void k_gemm2(const float* __restrict__ W2, const float* __restrict__ gma,
                        const float* __restrict__ bet, int n) {
    gemm_body<true>(g_agg, W2, n, blockIdx.x, gma, bet);
}

// ---------------- aggregation + fused BN stats (LAYER selects stats buffer) ----------------
template <int LAYER>
__global__ void k_agg_gather(int n) {
    __shared__ float s_val[8][128];
    __shared__ float s_sq [8][128];
    const int warp = threadIdx.x >> 5;
    const int lane = threadIdx.x & 31;
    const int node = blockIdx.x * 8 + warp;

    float4 acc = make_float4(0.f, 0.f, 0.f, 0.f);
    if (node < n) {
        const float dd = g_dis[node];
        acc = *(const float4*)&g_h[node * 128 + (lane << 2)];
        float dd2 = dd * dd;
        acc.x *= dd2; acc.y *= dd2; acc.z *= dd2; acc.w *= dd2;

        const int beg = g_row[node];
        const int end = g_row[node + 1];
        for (int base = beg; base < end; base += 32) {
            int idx = base + lane;
            int s = 0; float ns = 0.f;
            if (idx < end) {
                s = g_col[idx];
                ns = g_dis[s] * dd;
            }
            int cnt = min(32, end - base);
            #pragma unroll 4
            for (int k = 0; k < cnt; k++) {
                int   sk = __shfl_sync(0xffffffffu, s, k);
                float nk = __shfl_sync(0xffffffffu, ns, k);
                float4 v = *(const float4*)&g_h[sk * 128 + (lane << 2)];
                acc.x += v.x * nk; acc.y += v.y * nk;
                acc.z += v.z * nk; acc.w += v.w * nk;
            }
        }
        *(float4*)&g_agg[node * 128 + (lane << 2)] = acc;
    }

    *(float4*)&s_val[warp][lane << 2] = acc;
    *(float4*)&s_sq [warp][lane << 2] =
        make_float4(acc.x * acc.x, acc.y * acc.y, acc.z * acc.z, acc.w * acc.w);
    __syncthreads();

    const int c    = threadIdx.x & 127;
    const int half = threadIdx.x >> 7;
    float tot = 0.f;
    #pragma unroll
    for (int w = 0; w < 8; w++) tot += half ? s_sq[w][c] : s_val[w][c];
    float* dest = (LAYER == 1) ? (half ? g_sq1 : g_sum1) : (half ? g_sq2 : g_sum2);
    atomicAdd(&dest[c], tot);
}

// ---------------- pooling with inline layer-2 BN+ReLU (batch sorted) ----------------
__global__ void k_pool(const int* __restrict__ batch, const float* __restrict__ gma,
                       const float* __restrict__ bet, int n) {
    const int c = threadIdx.x;   // 128 cols
    float inv_n = 1.0f / (float)n;
    float mu  = g_sum2[c] * inv_n;
    float var = g_sq2[c] * inv_n - mu * mu;
    float scale = gma[c] * rsqrtf(var + BN_EPS);
    float shift = bet[c] - mu * scale;

    const int chunk = (n + gridDim.x - 1) / gridDim.x;
    const int i0 = blockIdx.x * chunk;
    const int i1 = min(n, i0 + chunk);
    if (i0 >= i1) return;

    int curg = batch[i0];
    float acc = 0.f, cacc = 0.f;
    for (int i = i0; i < i1; i++) {
        int g = batch[i];
        if (g != curg) {
            atomicAdd(&g_pool[curg * 128 + c], acc);
            if (c == 0) atomicAdd(&g_cnt[curg], cacc);
            acc = 0.f; cacc = 0.f; curg = g;
        }
        acc += fmaxf(fmaf(g_agg[i * 128 + c], scale, shift), 0.f);
        cacc += 1.f;
    }
    atomicAdd(&g_pool[curg * 128 + c], acc);
    if (c == 0) atomicAdd(&g_cnt[curg], cacc);
}

// block per graph: out[g] = (pool[g]/max(cnt,1)) @ Wout + bout; then tail-zero scratch
__global__ void k_out(const float* __restrict__ Wout, const float* __restrict__ bout,
                      float* __restrict__ out) {
    __shared__ float p[128];
    const int g = blockIdx.x;
    const int t = threadIdx.x;
    float c = fmaxf(g_cnt[g], 1.0f);
    p[t] = g_pool[g * 128 + t] / c;
    __syncthreads();

    // tail-zero for the next replay (globals are zero at module load for the first call)
    g_pool[g * 128 + t] = 0.f;
    if (t == 0) g_cnt[g] = 0.f;
    for (int i = g * 128 + t; i < NMAX; i += GNUM * 128) g_degi[i] = 0;

    if (t < ODIM) {
        float s = bout[t];
        #pragma unroll 16
        for (int f = 0; f < 128; f++) s += p[f] * Wout[f * ODIM + t];
        out[g * ODIM + t] = s;
    }
}

// ---------------- launch ----------------
extern "C" void kernel_launch(void* const* d_in, const int* in_sizes, int n_in,
                              void* d_out, int out_size) {
    const float* x     = (const float*)d_in[0];
    const int*   ei    = (const int*)d_in[1];     // int32 (JAX default int)
    const int*   batch = (const int*)d_in[2];
    const float* W1    = (const float*)d_in[3];
    // d_in[4] = b1: cancels in training-mode BatchNorm
    const float* g1    = (const float*)d_in[5];
    const float* be1   = (const float*)d_in[6];
    const float* W2    = (const float*)d_in[7];
    // d_in[8] = b2: cancels
    const float* g2    = (const float*)d_in[9];
    const float* be2   = (const float*)d_in[10];
    const float* Wout  = (const float*)d_in[11];
    const float* bout  = (const float*)d_in[12];
    float*       out   = (float*)d_out;

    const int n = in_sizes[0] / HDIM;
    const int E = in_sizes[1] / 2;
    const int* src = ei;
    const int* dst = ei + E;

    const int TB = 256;
    const int edgeBlocks     = (E + TB - 1) / TB;
    const int nodeWarpBlocks = (n + 7) / 8;
    const int gemmBlocks     = (n + 63) / 64;

    // 1: degree count (g_degi zero on entry via tail-zero/initial zero-init)
    k_deg_count<<<edgeBlocks, TB>>>(dst, E);
    // 2: scan -> row/cur/dis
    k_scan<<<1, 1024>>>(n);
    // 3: layer-1 GEMM  ||  CSR fill (independent, fused launch)
    k_l1<<<gemmBlocks + edgeBlocks, TB>>>(x, W1, src, dst, n, E, gemmBlocks);
    // 4: gather 1 (+stats into sum1/sq1)  <- profiled slot
    k_agg_gather<1><<<nodeWarpBlocks, TB>>>(n);
    // 5: layer-2 GEMM (BN1+ReLU inline from raw stats)
    k_gemm2<<<gemmBlocks, TB>>>(W2, g1, be1, n);
    // 6: gather 2 (+stats into sum2/sq2)
    k_agg_gather<2><<<nodeWarpBlocks, TB>>>(n);
    // 7: pooling (BN2+ReLU inline)
    k_pool<<<256, 128>>>(batch, g2, be2, n);
    // 8: output GEMV + tail-zero scratch
    k_out<<<GNUM, 128>>>(Wout, bout, out);
}

// round 15
// speedup vs baseline: 1.3714x; 1.0763x over previous
#include <cuda_runtime.h>

#define NMAX 50000
#define EMAX 800000
#define HDIM 128
#define GNUM 256
#define ODIM 10
#define BN_EPS 1e-5f

// ---------------- scratch: device globals (zero-initialized at module load) ----------------
__device__ __align__(16) float g_h  [NMAX * HDIM];   // GEMM output features
__device__ __align__(16) float g_agg[NMAX * HDIM];   // aggregation output
__device__ int   g_degi[NMAX];                        // ZERO at entry (tail-zeroed each call)
__device__ int   g_row [NMAX + 1];
__device__ int   g_cur [NMAX];
__device__ int   g_col [EMAX];
__device__ float g_dis [NMAX];
__device__ float g_sum1[HDIM], g_sq1[HDIM];           // layer-1 BN raw stats
__device__ float g_sum2[HDIM], g_sq2[HDIM];           // layer-2 BN raw stats
__device__ __align__(16) float g_pool[GNUM * HDIM];   // ZERO at entry (tail-zeroed)
__device__ float g_cnt [GNUM];                        // ZERO at entry (tail-zeroed)

// ---------------- CSR build ----------------
__global__ void k_deg_count(const int* __restrict__ dst, int E) {
    int e = blockIdx.x * blockDim.x + threadIdx.x;
    if (e < E) atomicAdd(&g_degi[dst[e]], 1);
}

// single block, 1024 threads: coalesced tiled exclusive scan of degi -> row (+cur, dis)
__global__ void k_scan(int n) {
    __shared__ int warpsum[32];
    __shared__ int s_base;
    const int t = threadIdx.x;
    const int lane = t & 31;
    const int wid = t >> 5;
    if (t == 0) s_base = 0;
    __syncthreads();

    for (int t0 = 0; t0 < n; t0 += 1024) {
        int i = t0 + t;
        int d = (i < n) ? g_degi[i] : 0;
        int v = d;
        #pragma unroll
        for (int off = 1; off < 32; off <<= 1) {
            int u = __shfl_up_sync(0xffffffffu, v, off);
            if (lane >= off) v += u;
        }
        if (lane == 31) warpsum[wid] = v;
        __syncthreads();
        if (wid == 0) {
            int w = warpsum[lane];
            #pragma unroll
            for (int off = 1; off < 32; off <<= 1) {
                int u = __shfl_up_sync(0xffffffffu, w, off);
                if (lane >= off) w += u;
            }
            warpsum[lane] = w;
        }
        __syncthreads();
        int base = s_base + (wid ? warpsum[wid - 1] : 0);
        int excl = base + v - d;
        if (i < n) {
            g_row[i] = excl;
            g_cur[i] = excl;
            g_dis[i] = rsqrtf((float)(d + 1));
        }
        __syncthreads();
        if (t == 0) s_base += warpsum[31];
        __syncthreads();
    }
    if (t == 0) g_row[n] = s_base;
}

// ---------------- GEMM body: g_h = A @ W (256 threads, 64-row tile) ----------------
template <bool APPLY_BN>
__device__ __forceinline__ void gemm_body(const float* __restrict__ A, const float* __restrict__ W,
                                          int n, int blk,
                                          const float* __restrict__ gma, const float* __restrict__ bet) {
    __shared__ float sW[32][128];
    __shared__ float sA[64][33];
    __shared__ float s_scale[128], s_shift[128];
    const int t = threadIdx.x;       // 256
    const int row0 = blk * 64;
    const int tx = t & 15;
    const int ty = t >> 4;

    if (APPLY_BN) {
        if (t < 128) {
            float inv_n = 1.0f / (float)n;
            float mu  = g_sum1[t] * inv_n;
            float var = g_sq1[t] * inv_n - mu * mu;
            float sc  = gma[t] * rsqrtf(var + BN_EPS);
            s_scale[t] = sc;
            s_shift[t] = bet[t] - mu * sc;
        }
        __syncthreads();
    }

    float acc[4][8];
    #pragma unroll
    for (int r = 0; r < 4; r++)
        #pragma unroll
        for (int c = 0; c < 8; c++) acc[r][c] = 0.f;

    for (int kc = 0; kc < 4; kc++) {
        const int k0 = kc * 32;
        const float4* W4 = (const float4*)(W + k0 * 128);
        float4* sW4 = (float4*)&sW[0][0];
        #pragma unroll
        for (int i = t; i < 1024; i += 256) sW4[i] = W4[i];
        #pragma unroll
        for (int i = t; i < 512; i += 256) {
            int r = i >> 3, c4 = i & 7;
            int gr = row0 + r;
            int col = k0 + c4 * 4;
            float4 v = make_float4(0.f, 0.f, 0.f, 0.f);
            if (gr < n) {
                v = *(const float4*)(A + gr * 128 + col);
                if (APPLY_BN) {
                    v.x = fmaxf(fmaf(v.x, s_scale[col + 0], s_shift[col + 0]), 0.f);
                    v.y = fmaxf(fmaf(v.y, s_scale[col + 1], s_shift[col + 1]), 0.f);
                    v.z = fmaxf(fmaf(v.z, s_scale[col + 2], s_shift[col + 2]), 0.f);
                    v.w = fmaxf(fmaf(v.w, s_scale[col + 3], s_shift[col + 3]), 0.f);
                }
            }
            sA[r][c4 * 4 + 0] = v.x; sA[r][c4 * 4 + 1] = v.y;
            sA[r][c4 * 4 + 2] = v.z; sA[r][c4 * 4 + 3] = v.w;
        }
        __syncthreads();

        #pragma unroll
        for (int k = 0; k < 32; k++) {
            float4 w0 = *(const float4*)&sW[k][tx * 8];
            float4 w1 = *(const float4*)&sW[k][tx * 8 + 4];
            float ar[4];
            #pragma unroll
            for (int r = 0; r < 4; r++) ar[r] = sA[ty * 4 + r][k];
            float wc[8] = {w0.x, w0.y, w0.z, w0.w, w1.x, w1.y, w1.z, w1.w};
            #pragma unroll
            for (int r = 0; r < 4; r++)
                #pragma unroll
                for (int c = 0; c < 8; c++) acc[r][c] += ar[r] * wc[c];
        }
        __syncthreads();
    }

    #pragma unroll
    for (int r = 0; r < 4; r++) {
        int gr = row0 + ty * 4 + r;
        if (gr < n) {
            *(float4*)&g_h[gr * 128 + tx * 8]     = make_float4(acc[r][0], acc[r][1], acc[r][2], acc[r][3]);
            *(float4*)&g_h[gr * 128 + tx * 8 + 4] = make_float4(acc[r][4], acc[r][5], acc[r][6], acc[r][7]);
        }
    }
}

// ---------------- fused layer-1 GEMM + CSR fill ----------------
__global__ void k_l1(const float* __restrict__ x, const float* __restrict__ W1,
                     const int* __restrict__ src, const int* __restrict__ dst,
                     int n, int E, int gemmBlocks) {
    if ((int)blockIdx.x < gemmBlocks) {
        if (blockIdx.x == 0 && threadIdx.x < 128) {
            g_sum1[threadIdx.x] = 0.f; g_sq1[threadIdx.x] = 0.f;
            g_sum2[threadIdx.x] = 0.f; g_sq2[threadIdx.x] = 0.f;
        }
        gemm_body<false>(x, W1, n, blockIdx.x, nullptr, nullptr);
    } else {
        int e = ((int)blockIdx.x - gemmBlocks) * (int)blockDim.x + (int)threadIdx.x;
        if (e < E) {
            int d = dst[e];
            int p = atomicAdd(&g_cur[d], 1);
            g_col[p] = src[e];
        }
    }
}

__global__ void k_gemm2(const float* __restrict__ W2, const float* __restrict__ gma,
                        const float* __restrict__ bet, int n) {
    gemm_body<true>(g_agg, W2, n, blockIdx.x, gma, bet);
}

// ---------------- aggregation + fused BN stats ----------------
// warp per dst node; smem edge staging; dual accumulators; 8 loads in flight.
template <int LAYER>
__global__ void k_agg_gather(int n) {
    __shared__ float s_val[8][128];
    __shared__ float s_sq [8][128];
    __shared__ int   s_idx[8][32];
    __shared__ float s_nrm[8][32];
    const int warp = threadIdx.x >> 5;
    const int lane = threadIdx.x & 31;
    const int node = blockIdx.x * 8 + warp;
    const int fofs = lane << 2;

    float4 acc0 = make_float4(0.f, 0.f, 0.f, 0.f);
    float4 acc1 = make_float4(0.f, 0.f, 0.f, 0.f);
    if (node < n) {
        const float dd = g_dis[node];
        float4 self = *(const float4*)&g_h[node * 128 + fofs];
        const float dd2 = dd * dd;
        acc0.x = self.x * dd2; acc0.y = self.y * dd2;
        acc0.z = self.z * dd2; acc0.w = self.w * dd2;

        const int beg = g_row[node];
        const int end = g_row[node + 1];
        for (int base = beg; base < end; base += 32) {
            int idx = base + lane;
            if (idx < end) {
                int s = g_col[idx];
                s_idx[warp][lane] = s;
                s_nrm[warp][lane] = g_dis[s] * dd;
            }
            __syncwarp();
            const int cnt = min(32, end - base);
            int k = 0;
            #pragma unroll 4
            for (; k + 2 <= cnt; k += 2) {
                int   sk0 = s_idx[warp][k];
                int   sk1 = s_idx[warp][k + 1];
                float nk0 = s_nrm[warp][k];
                float nk1 = s_nrm[warp][k + 1];
                float4 v0 = *(const float4*)&g_h[sk0 * 128 + fofs];
                float4 v1 = *(const float4*)&g_h[sk1 * 128 + fofs];
                acc0.x += v0.x * nk0; acc0.y += v0.y * nk0;
                acc0.z += v0.z * nk0; acc0.w += v0.w * nk0;
                acc1.x += v1.x * nk1; acc1.y += v1.y * nk1;
                acc1.z += v1.z * nk1; acc1.w += v1.w * nk1;
            }
            if (k < cnt) {
                int   sk = s_idx[warp][k];
                float nk = s_nrm[warp][k];
                float4 v = *(const float4*)&g_h[sk * 128 + fofs];
                acc0.x += v.x * nk; acc0.y += v.y * nk;
                acc0.z += v.z * nk; acc0.w += v.w * nk;
            }
            __syncwarp();
        }
        acc0.x += acc1.x; acc0.y += acc1.y; acc0.z += acc1.z; acc0.w += acc1.w;
        *(float4*)&g_agg[node * 128 + fofs] = acc0;
    }

    *(float4*)&s_val[warp][fofs] = acc0;
    *(float4*)&s_sq [warp][fofs] =
        make_float4(acc0.x * acc0.x, acc0.y * acc0.y, acc0.z * acc0.z, acc0.w * acc0.w);
    __syncthreads();

    const int c    = threadIdx.x & 127;
    const int half = threadIdx.x >> 7;
    float tot = 0.f;
    #pragma unroll
    for (int w = 0; w < 8; w++) tot += half ? s_sq[w][c] : s_val[w][c];
    float* dest = (LAYER == 1) ? (half ? g_sq1 : g_sum1) : (half ? g_sq2 : g_sum2);
    atomicAdd(&dest[c], tot);
}

// ---------------- pooling with inline layer-2 BN+ReLU (batch sorted) ----------------
__global__ void k_pool(const int* __restrict__ batch, const float* __restrict__ gma,
                       const float* __restrict__ bet, int n) {
    const int c = threadIdx.x;   // 128 cols
    float inv_n = 1.0f / (float)n;
    float mu  = g_sum2[c] * inv_n;
    float var = g_sq2[c] * inv_n - mu * mu;
    float scale = gma[c] * rsqrtf(var + BN_EPS);
    float shift = bet[c] - mu * scale;

    const int chunk = (n + gridDim.x - 1) / gridDim.x;
    const int i0 = blockIdx.x * chunk;
    const int i1 = min(n, i0 + chunk);
    if (i0 >= i1) return;

    int curg = batch[i0];
    float acc = 0.f, cacc = 0.f;
    for (int i = i0; i < i1; i++) {
        int g = batch[i];
        if (g != curg) {
            atomicAdd(&g_pool[curg * 128 + c], acc);
            if (c == 0) atomicAdd(&g_cnt[curg], cacc);
            acc = 0.f; cacc = 0.f; curg = g;
        }
        acc += fmaxf(fmaf(g_agg[i * 128 + c], scale, shift), 0.f);
        cacc += 1.f;
    }
    atomicAdd(&g_pool[curg * 128 + c], acc);
    if (c == 0) atomicAdd(&g_cnt[curg], cacc);
}

// block per graph: out[g] = (pool[g]/max(cnt,1)) @ Wout + bout; then tail-zero scratch
__global__ void k_out(const float* __restrict__ Wout, const float* __restrict__ bout,
                      float* __restrict__ out) {
    __shared__ float p[128];
    const int g = blockIdx.x;
    const int t = threadIdx.x;
    float c = fmaxf(g_cnt[g], 1.0f);
    p[t] = g_pool[g * 128 + t] / c;
    __syncthreads();

    g_pool[g * 128 + t] = 0.f;
    if (t == 0) g_cnt[g] = 0.f;
    for (int i = g * 128 + t; i < NMAX; i += GNUM * 128) g_degi[i] = 0;

    if (t < ODIM) {
        float s = bout[t];
        #pragma unroll 16
        for (int f = 0; f < 128; f++) s += p[f] * Wout[f * ODIM + t];
        out[g * ODIM + t] = s;
    }
}

// ---------------- launch ----------------
extern "C" void kernel_launch(void* const* d_in, const int* in_sizes, int n_in,
                              void* d_out, int out_size) {
    const float* x     = (const float*)d_in[0];
    const int*   ei    = (const int*)d_in[1];     // int32 (JAX default int)
    const int*   batch = (const int*)d_in[2];
    const float* W1    = (const float*)d_in[3];
    const float* g1    = (const float*)d_in[5];
    const float* be1   = (const float*)d_in[6];
    const float* W2    = (const float*)d_in[7];
    const float* g2    = (const float*)d_in[9];
    const float* be2   = (const float*)d_in[10];
    const float* Wout  = (const float*)d_in[11];
    const float* bout  = (const float*)d_in[12];
    float*       out   = (float*)d_out;

    const int n = in_sizes[0] / HDIM;
    const int E = in_sizes[1] / 2;
    const int* src = ei;
    const int* dst = ei + E;

    const int TB = 256;
    const int edgeBlocks     = (E + TB - 1) / TB;
    const int nodeWarpBlocks = (n + 7) / 8;
    const int gemmBlocks     = (n + 63) / 64;

    k_deg_count<<<edgeBlocks, TB>>>(dst, E);
    k_scan<<<1, 1024>>>(n);
    k_l1<<<gemmBlocks + edgeBlocks, TB>>>(x, W1, src, dst, n, E, gemmBlocks);
    k_agg_gather<1><<<nodeWarpBlocks, TB>>>(n);       // <- profiled slot
    k_gemm2<<<gemmBlocks, TB>>>(W2, g1, be1, n);
    k_agg_gather<2><<<nodeWarpBlocks, TB>>>(n);
    k_pool<<<512, 128>>>(batch, g2, be2, n);
    k_out<<<GNUM, 128>>>(Wout, bout, out);
}

// round 16
// speedup vs baseline: 1.4816x; 1.0804x over previous
#include <cuda_runtime.h>
#include <cuda_fp16.h>

#define NMAX 50000
#define EMAX 800000
#define HDIM 128
#define GNUM 256
#define ODIM 10
#define BN_EPS 1e-5f

// ---------------- scratch: device globals (zero-initialized at module load) ----------------
__device__ __align__(16) __half g_h16[NMAX * HDIM];  // GEMM output features (fp16!)
__device__ __align__(16) float  g_agg[NMAX * HDIM];  // aggregation output (fp32)
__device__ int   g_degi[NMAX];                        // ZERO at entry (tail-zeroed each call)
__device__ int   g_row [NMAX + 1];
__device__ int   g_cur [NMAX];
__device__ int   g_col [EMAX];
__device__ float g_dis [NMAX];
__device__ float g_sum1[HDIM], g_sq1[HDIM];           // layer-1 BN raw stats
__device__ float g_sum2[HDIM], g_sq2[HDIM];           // layer-2 BN raw stats
__device__ __align__(16) float g_pool[GNUM * HDIM];   // ZERO at entry (tail-zeroed)
__device__ float g_cnt [GNUM];                        // ZERO at entry (tail-zeroed)

// ---------------- CSR build ----------------
__global__ void k_deg_count(const int* __restrict__ dst, int E) {
    int e = blockIdx.x * blockDim.x + threadIdx.x;
    if (e < E) atomicAdd(&g_degi[dst[e]], 1);
}

// single block, 1024 threads: coalesced tiled exclusive scan of degi -> row (+cur, dis)
__global__ void k_scan(int n) {
    __shared__ int warpsum[32];
    __shared__ int s_base;
    const int t = threadIdx.x;
    const int lane = t & 31;
    const int wid = t >> 5;
    if (t == 0) s_base = 0;
    __syncthreads();

    for (int t0 = 0; t0 < n; t0 += 1024) {
        int i = t0 + t;
        int d = (i < n) ? g_degi[i] : 0;
        int v = d;
        #pragma unroll
        for (int off = 1; off < 32; off <<= 1) {
            int u = __shfl_up_sync(0xffffffffu, v, off);
            if (lane >= off) v += u;
        }
        if (lane == 31) warpsum[wid] = v;
        __syncthreads();
        if (wid == 0) {
            int w = warpsum[lane];
            #pragma unroll
            for (int off = 1; off < 32; off <<= 1) {
                int u = __shfl_up_sync(0xffffffffu, w, off);
                if (lane >= off) w += u;
            }
            warpsum[lane] = w;
        }
        __syncthreads();
        int base = s_base + (wid ? warpsum[wid - 1] : 0);
        int excl = base + v - d;
        if (i < n) {
            g_row[i] = excl;
            g_cur[i] = excl;
            g_dis[i] = rsqrtf((float)(d + 1));
        }
        __syncthreads();
        if (t == 0) s_base += warpsum[31];
        __syncthreads();
    }
    if (t == 0) g_row[n] = s_base;
}

// ---------------- GEMM body: g_h16 = A @ W (fp16 store; 256 threads, 64-row tile) ----------------
template <bool APPLY_BN>
__device__ __forceinline__ void gemm_body(const float* __restrict__ A, const float* __restrict__ W,
                                          int n, int blk,
                                          const float* __restrict__ gma, const float* __restrict__ bet) {
    __shared__ float sW[32][128];
    __shared__ float sA[64][33];
    __shared__ float s_scale[128], s_shift[128];
    const int t = threadIdx.x;       // 256
    const int row0 = blk * 64;
    const int tx = t & 15;
    const int ty = t >> 4;

    if (APPLY_BN) {
        if (t < 128) {
            float inv_n = 1.0f / (float)n;
            float mu  = g_sum1[t] * inv_n;
            float var = g_sq1[t] * inv_n - mu * mu;
            float sc  = gma[t] * rsqrtf(var + BN_EPS);
            s_scale[t] = sc;
            s_shift[t] = bet[t] - mu * sc;
        }
        __syncthreads();
    }

    float acc[4][8];
    #pragma unroll
    for (int r = 0; r < 4; r++)
        #pragma unroll
        for (int c = 0; c < 8; c++) acc[r][c] = 0.f;

    for (int kc = 0; kc < 4; kc++) {
        const int k0 = kc * 32;
        const float4* W4 = (const float4*)(W + k0 * 128);
        float4* sW4 = (float4*)&sW[0][0];
        #pragma unroll
        for (int i = t; i < 1024; i += 256) sW4[i] = W4[i];
        #pragma unroll
        for (int i = t; i < 512; i += 256) {
            int r = i >> 3, c4 = i & 7;
            int gr = row0 + r;
            int col = k0 + c4 * 4;
            float4 v = make_float4(0.f, 0.f, 0.f, 0.f);
            if (gr < n) {
                v = *(const float4*)(A + gr * 128 + col);
                if (APPLY_BN) {
                    v.x = fmaxf(fmaf(v.x, s_scale[col + 0], s_shift[col + 0]), 0.f);
                    v.y = fmaxf(fmaf(v.y, s_scale[col + 1], s_shift[col + 1]), 0.f);
                    v.z = fmaxf(fmaf(v.z, s_scale[col + 2], s_shift[col + 2]), 0.f);
                    v.w = fmaxf(fmaf(v.w, s_scale[col + 3], s_shift[col + 3]), 0.f);
                }
            }
            sA[r][c4 * 4 + 0] = v.x; sA[r][c4 * 4 + 1] = v.y;
            sA[r][c4 * 4 + 2] = v.z; sA[r][c4 * 4 + 3] = v.w;
        }
        __syncthreads();

        #pragma unroll
        for (int k = 0; k < 32; k++) {
            float4 w0 = *(const float4*)&sW[k][tx * 8];
            float4 w1 = *(const float4*)&sW[k][tx * 8 + 4];
            float ar[4];
            #pragma unroll
            for (int r = 0; r < 4; r++) ar[r] = sA[ty * 4 + r][k];
            float wc[8] = {w0.x, w0.y, w0.z, w0.w, w1.x, w1.y, w1.z, w1.w};
            #pragma unroll
            for (int r = 0; r < 4; r++)
                #pragma unroll
                for (int c = 0; c < 8; c++) acc[r][c] += ar[r] * wc[c];
        }
        __syncthreads();
    }

    // fp16 epilogue: 8 floats -> 8 halves -> one 16B store
    #pragma unroll
    for (int r = 0; r < 4; r++) {
        int gr = row0 + ty * 4 + r;
        if (gr < n) {
            __half2 hh[4];
            hh[0] = __floats2half2_rn(acc[r][0], acc[r][1]);
            hh[1] = __floats2half2_rn(acc[r][2], acc[r][3]);
            hh[2] = __floats2half2_rn(acc[r][4], acc[r][5]);
            hh[3] = __floats2half2_rn(acc[r][6], acc[r][7]);
            *(float4*)&g_h16[gr * 128 + tx * 8] = *(float4*)hh;
        }
    }
}

// ---------------- fused layer-1 GEMM + CSR fill ----------------
__global__ void k_l1(const float* __restrict__ x, const float* __restrict__ W1,
                     const int* __restrict__ src, const int* __restrict__ dst,
                     int n, int E, int gemmBlocks) {
    if ((int)blockIdx.x < gemmBlocks) {
        if (blockIdx.x == 0 && threadIdx.x < 128) {
            g_sum1[threadIdx.x] = 0.f; g_sq1[threadIdx.x] = 0.f;
            g_sum2[threadIdx.x] = 0.f; g_sq2[threadIdx.x] = 0.f;
        }
        gemm_body<false>(x, W1, n, blockIdx.x, nullptr, nullptr);
    } else {
        int e = ((int)blockIdx.x - gemmBlocks) * (int)blockDim.x + (int)threadIdx.x;
        if (e < E) {
            int d = dst[e];
            int p = atomicAdd(&g_cur[d], 1);
            g_col[p] = src[e];
        }
    }
}

__global__ void k_gemm2(const float* __restrict__ W2, const float* __restrict__ gma,
                        const float* __restrict__ bet, int n) {
    gemm_body<true>(g_agg, W2, n, blockIdx.x, gma, bet);
}

// ---------------- aggregation + fused BN stats ----------------
// warp per dst node; fp16 feature loads (8B/lane/edge), fp32 accumulation.
template <int LAYER>
__global__ void k_agg_gather(int n) {
    __shared__ float s_val[8][128];
    __shared__ float s_sq [8][128];
    __shared__ int   s_idx[8][32];
    __shared__ float s_nrm[8][32];
    const int warp = threadIdx.x >> 5;
    const int lane = threadIdx.x & 31;
    const int node = blockIdx.x * 8 + warp;
    const int fofs = lane << 2;        // 4 features per lane

    float4 acc0 = make_float4(0.f, 0.f, 0.f, 0.f);
    float4 acc1 = make_float4(0.f, 0.f, 0.f, 0.f);
    if (node < n) {
        const float dd = g_dis[node];
        const float dd2 = dd * dd;
        {
            uint2 raw = *(const uint2*)&g_h16[node * 128 + fofs];
            float2 f01 = __half22float2(*(__half2*)&raw.x);
            float2 f23 = __half22float2(*(__half2*)&raw.y);
            acc0.x = f01.x * dd2; acc0.y = f01.y * dd2;
            acc0.z = f23.x * dd2; acc0.w = f23.y * dd2;
        }

        const int beg = g_row[node];
        const int end = g_row[node + 1];
        for (int base = beg; base < end; base += 32) {
            int idx = base + lane;
            if (idx < end) {
                int s = g_col[idx];
                s_idx[warp][lane] = s;
                s_nrm[warp][lane] = g_dis[s] * dd;
            }
            __syncwarp();
            const int cnt = min(32, end - base);
            int k = 0;
            #pragma unroll 4
            for (; k + 2 <= cnt; k += 2) {
                int   sk0 = s_idx[warp][k];
                int   sk1 = s_idx[warp][k + 1];
                float nk0 = s_nrm[warp][k];
                float nk1 = s_nrm[warp][k + 1];
                uint2 r0 = *(const uint2*)&g_h16[sk0 * 128 + fofs];
                uint2 r1 = *(const uint2*)&g_h16[sk1 * 128 + fofs];
                float2 a01 = __half22float2(*(__half2*)&r0.x);
                float2 a23 = __half22float2(*(__half2*)&r0.y);
                float2 b01 = __half22float2(*(__half2*)&r1.x);
                float2 b23 = __half22float2(*(__half2*)&r1.y);
                acc0.x += a01.x * nk0; acc0.y += a01.y * nk0;
                acc0.z += a23.x * nk0; acc0.w += a23.y * nk0;
                acc1.x += b01.x * nk1; acc1.y += b01.y * nk1;
                acc1.z += b23.x * nk1; acc1.w += b23.y * nk1;
            }
            if (k < cnt) {
                int   sk = s_idx[warp][k];
                float nk = s_nrm[warp][k];
                uint2 r0 = *(const uint2*)&g_h16[sk * 128 + fofs];
                float2 a01 = __half22float2(*(__half2*)&r0.x);
                float2 a23 = __half22float2(*(__half2*)&r0.y);
                acc0.x += a01.x * nk; acc0.y += a01.y * nk;
                acc0.z += a23.x * nk; acc0.w += a23.y * nk;
            }
            __syncwarp();
        }
        acc0.x += acc1.x; acc0.y += acc1.y; acc0.z += acc1.z; acc0.w += acc1.w;
        *(float4*)&g_agg[node * 128 + fofs] = acc0;
    }

    *(float4*)&s_val[warp][fofs] = acc0;
    *(float4*)&s_sq [warp][fofs] =
        make_float4(acc0.x * acc0.x, acc0.y * acc0.y, acc0.z * acc0.z, acc0.w * acc0.w);
    __syncthreads();

    const int c    = threadIdx.x & 127;
    const int half = threadIdx.x >> 7;
    float tot = 0.f;
    #pragma unroll
    for (int w = 0; w < 8; w++) tot += half ? s_sq[w][c] : s_val[w][c];
    float* dest = (LAYER == 1) ? (half ? g_sq1 : g_sum1) : (half ? g_sq2 : g_sum2);
    atomicAdd(&dest[c], tot);
}

// ---------------- pooling with inline layer-2 BN+ReLU (batch sorted) ----------------
__global__ void k_pool(const int* __restrict__ batch, const float* __restrict__ gma,
                       const float* __restrict__ bet, int n) {
    const int c = threadIdx.x;   // 128 cols
    float inv_n = 1.0f / (float)n;
    float mu  = g_sum2[c] * inv_n;
    float var = g_sq2[c] * inv_n - mu * mu;
    float scale = gma[c] * rsqrtf(var + BN_EPS);
    float shift = bet[c] - mu * scale;

    const int chunk = (n + gridDim.x - 1) / gridDim.x;
    const int i0 = blockIdx.x * chunk;
    const int i1 = min(n, i0 + chunk);
    if (i0 >= i1) return;

    int curg = batch[i0];
    float acc = 0.f, cacc = 0.f;
    for (int i = i0; i < i1; i++) {
        int g = batch[i];
        if (g != curg) {
            atomicAdd(&g_pool[curg * 128 + c], acc);
            if (c == 0) atomicAdd(&g_cnt[curg], cacc);
            acc = 0.f; cacc = 0.f; curg = g;
        }
        acc += fmaxf(fmaf(g_agg[i * 128 + c], scale, shift), 0.f);
        cacc += 1.f;
    }
    atomicAdd(&g_pool[curg * 128 + c], acc);
    if (c == 0) atomicAdd(&g_cnt[curg], cacc);
}

// block per graph: out[g] = (pool[g]/max(cnt,1)) @ Wout + bout; then tail-zero scratch
__global__ void k_out(const float* __restrict__ Wout, const float* __restrict__ bout,
                      float* __restrict__ out) {
    __shared__ float p[128];
    const int g = blockIdx.x;
    const int t = threadIdx.x;
    float c = fmaxf(g_cnt[g], 1.0f);
    p[t] = g_pool[g * 128 + t] / c;
    __syncthreads();

    g_pool[g * 128 + t] = 0.f;
    if (t == 0) g_cnt[g] = 0.f;
    for (int i = g * 128 + t; i < NMAX; i += GNUM * 128) g_degi[i] = 0;

    if (t < ODIM) {
        float s = bout[t];
        #pragma unroll 16
        for (int f = 0; f < 128; f++) s += p[f] * Wout[f * ODIM + t];
        out[g * ODIM + t] = s;
    }
}

// ---------------- launch ----------------
extern "C" void kernel_launch(void* const* d_in, const int* in_sizes, int n_in,
                              void* d_out, int out_size) {
    const float* x     = (const float*)d_in[0];
    const int*   ei    = (const int*)d_in[1];     // int32 (JAX default int)
    const int*   batch = (const int*)d_in[2];
    const float* W1    = (const float*)d_in[3];
    const float* g1    = (const float*)d_in[5];
    const float* be1   = (const float*)d_in[6];
    const float* W2    = (const float*)d_in[7];
    const float* g2    = (const float*)d_in[9];
    const float* be2   = (const float*)d_in[10];
    const float* Wout  = (const float*)d_in[11];
    const float* bout  = (const float*)d_in[12];
    float*       out   = (float*)d_out;

    const int n = in_sizes[0] / HDIM;
    const int E = in_sizes[1] / 2;
    const int* src = ei;
    const int* dst = ei + E;

    const int TB = 256;
    const int edgeBlocks     = (E + TB - 1) / TB;
    const int nodeWarpBlocks = (n + 7) / 8;
    const int gemmBlocks     = (n + 63) / 64;

    k_deg_count<<<edgeBlocks, TB>>>(dst, E);
    k_scan<<<1, 1024>>>(n);
    k_l1<<<gemmBlocks + edgeBlocks, TB>>>(x, W1, src, dst, n, E, gemmBlocks);
    k_agg_gather<1><<<nodeWarpBlocks, TB>>>(n);       // <- profiled slot
    k_gemm2<<<gemmBlocks, TB>>>(W2, g1, be1, n);
    k_agg_gather<2><<<nodeWarpBlocks, TB>>>(n);
    k_pool<<<512, 128>>>(batch, g2, be2, n);
    k_out<<<GNUM, 128>>>(Wout, bout, out);
}

// round 17
// speedup vs baseline: 1.6109x; 1.0873x over previous
#include <cuda_runtime.h>
#include <cuda_fp16.h>
#include <mma.h>

using namespace nvcuda;

#define NMAX 50000
#define EMAX 800000
#define HDIM 128
#define GNUM 256
#define ODIM 10
#define BN_EPS 1e-5f

// ---------------- scratch: device globals (zero-initialized at module load) ----------------
__device__ __align__(16) __half g_h16[NMAX * HDIM];  // GEMM output features (fp16)
__device__ __align__(16) float  g_agg[NMAX * HDIM];  // aggregation output (fp32)
__device__ int   g_degi[NMAX];                        // ZERO at entry (tail-zeroed each call)
__device__ int   g_row [NMAX + 1];
__device__ int   g_cur [NMAX];
__device__ int   g_col [EMAX];
__device__ float g_dis [NMAX];
__device__ float g_sum1[HDIM], g_sq1[HDIM];
__device__ float g_sum2[HDIM], g_sq2[HDIM];
__device__ __align__(16) float g_pool[GNUM * HDIM];
__device__ float g_cnt [GNUM];

// ---------------- CSR build ----------------
__global__ void k_deg_count(const int* __restrict__ dst, int E) {
    int e = blockIdx.x * blockDim.x + threadIdx.x;
    if (e < E) atomicAdd(&g_degi[dst[e]], 1);
}

__global__ void k_scan(int n) {
    __shared__ int warpsum[32];
    __shared__ int s_base;
    const int t = threadIdx.x;
    const int lane = t & 31;
    const int wid = t >> 5;
    if (t == 0) s_base = 0;
    __syncthreads();

    for (int t0 = 0; t0 < n; t0 += 1024) {
        int i = t0 + t;
        int d = (i < n) ? g_degi[i] : 0;
        int v = d;
        #pragma unroll
        for (int off = 1; off < 32; off <<= 1) {
            int u = __shfl_up_sync(0xffffffffu, v, off);
            if (lane >= off) v += u;
        }
        if (lane == 31) warpsum[wid] = v;
        __syncthreads();
        if (wid == 0) {
            int w = warpsum[lane];
            #pragma unroll
            for (int off = 1; off < 32; off <<= 1) {
                int u = __shfl_up_sync(0xffffffffu, w, off);
                if (lane >= off) w += u;
            }
            warpsum[lane] = w;
        }
        __syncthreads();
        int base = s_base + (wid ? warpsum[wid - 1] : 0);
        int excl = base + v - d;
        if (i < n) {
            g_row[i] = excl;
            g_cur[i] = excl;
            g_dis[i] = rsqrtf((float)(d + 1));
        }
        __syncthreads();
        if (t == 0) s_base += warpsum[31];
        __syncthreads();
    }
    if (t == 0) g_row[n] = s_base;
}

// ---------------- wmma GEMM body: g_h16 = half(A @ W) ----------------
// 256 threads = 8 warps. Block tile 64x128, K chunked x32, fp16 HMMA, fp32 acc.
// smem union: phase 1 holds fp16 A-chunk (64x40) + W-chunk (32x128); phase 2 fp32 stage 64x132.
template <bool APPLY_BN>
__device__ __forceinline__ void gemm_body(const float* __restrict__ A, const float* __restrict__ W,
                                          int n, int blk,
                                          const float* __restrict__ gma, const float* __restrict__ bet) {
    __shared__ __align__(16) unsigned char sbuf[64 * 132 * 4];   // 33792 B
    __shared__ float s_scale[128], s_shift[128];
    __half (*sA)[40]  = (__half(*)[40])sbuf;                     // 5120 B
    __half (*sW)[128] = (__half(*)[128])(sbuf + 5120);           // 8192 B
    float  (*stage)[132] = (float(*)[132])sbuf;                  // epilogue reuse

    const int t = threadIdx.x;
    const int wid = t >> 5;
    const int row0 = blk * 64;
    const int warp_m = wid & 3;        // 4 row-tiles of 16
    const int warp_n = wid >> 2;       // 2 col-halves of 64

    if (APPLY_BN) {
        if (t < 128) {
            float inv_n = 1.0f / (float)n;
            float mu  = g_sum1[t] * inv_n;
            float var = g_sq1[t] * inv_n - mu * mu;
            float sc  = gma[t] * rsqrtf(var + BN_EPS);
            s_scale[t] = sc;
            s_shift[t] = bet[t] - mu * sc;
        }
        __syncthreads();
    }

    wmma::fragment<wmma::accumulator, 16, 16, 16, float> acc[4];
    #pragma unroll
    for (int j = 0; j < 4; j++) wmma::fill_fragment(acc[j], 0.f);

    for (int kc = 0; kc < 4; kc++) {
        const int k0 = kc * 32;
        // A chunk: 64 rows x 32 cols -> fp16 (with optional BN+ReLU). 512 float4 slots.
        #pragma unroll
        for (int i = t; i < 512; i += 256) {
            int r = i >> 3, c4 = i & 7;
            int gr = row0 + r;
            int col = k0 + c4 * 4;
            float4 v = make_float4(0.f, 0.f, 0.f, 0.f);
            if (gr < n) {
                v = *(const float4*)(A + gr * 128 + col);
                if (APPLY_BN) {
                    v.x = fmaxf(fmaf(v.x, s_scale[col + 0], s_shift[col + 0]), 0.f);
                    v.y = fmaxf(fmaf(v.y, s_scale[col + 1], s_shift[col + 1]), 0.f);
                    v.z = fmaxf(fmaf(v.z, s_scale[col + 2], s_shift[col + 2]), 0.f);
                    v.w = fmaxf(fmaf(v.w, s_scale[col + 3], s_shift[col + 3]), 0.f);
                }
            }
            __half2 h01 = __floats2half2_rn(v.x, v.y);
            __half2 h23 = __floats2half2_rn(v.z, v.w);
            uint2 packed = make_uint2(*(unsigned*)&h01, *(unsigned*)&h23);
            *(uint2*)&sA[r][c4 * 4] = packed;
        }
        // W chunk: 32 rows(k) x 128 cols -> fp16. 16 halves per thread.
        {
            int r = t >> 3;            // 0..31
            int cg = (t & 7) * 16;     // 16-col group
            const float4* wp = (const float4*)(W + (k0 + r) * 128 + cg);
            float4 w0 = wp[0], w1 = wp[1], w2 = wp[2], w3 = wp[3];
            __half2 h[8];
            h[0] = __floats2half2_rn(w0.x, w0.y); h[1] = __floats2half2_rn(w0.z, w0.w);
            h[2] = __floats2half2_rn(w1.x, w1.y); h[3] = __floats2half2_rn(w1.z, w1.w);
            h[4] = __floats2half2_rn(w2.x, w2.y); h[5] = __floats2half2_rn(w2.z, w2.w);
            h[6] = __floats2half2_rn(w3.x, w3.y); h[7] = __floats2half2_rn(w3.z, w3.w);
            *(uint4*)&sW[r][cg]     = *(uint4*)&h[0];
            *(uint4*)&sW[r][cg + 8] = *(uint4*)&h[4];
        }
        __syncthreads();

        #pragma unroll
        for (int ks = 0; ks < 32; ks += 16) {
            wmma::fragment<wmma::matrix_a, 16, 16, 16, __half, wmma::row_major> a_frag;
            wmma::load_matrix_sync(a_frag, &sA[warp_m * 16][ks], 40);
            #pragma unroll
            for (int j = 0; j < 4; j++) {
                wmma::fragment<wmma::matrix_b, 16, 16, 16, __half, wmma::row_major> b_frag;
                wmma::load_matrix_sync(b_frag, &sW[ks][warp_n * 64 + j * 16], 128);
                wmma::mma_sync(acc[j], a_frag, b_frag, acc[j]);
            }
        }
        __syncthreads();
    }

    // epilogue: acc -> fp32 stage -> packed fp16 global
    #pragma unroll
    for (int j = 0; j < 4; j++)
        wmma::store_matrix_sync(&stage[warp_m * 16][warp_n * 64 + j * 16], acc[j], 132, wmma::mem_row_major);
    __syncthreads();

    {
        int r = t >> 2;               // 0..63
        int cg = (t & 3) * 32;        // 32-col group
        int gr = row0 + r;
        if (gr < n) {
            #pragma unroll
            for (int s = 0; s < 2; s++) {           // two float4-groups of 16 cols
                float4 f0 = *(float4*)&stage[r][cg + s * 16];
                float4 f1 = *(float4*)&stage[r][cg + s * 16 + 4];
                float4 f2 = *(float4*)&stage[r][cg + s * 16 + 8];
                float4 f3 = *(float4*)&stage[r][cg + s * 16 + 12];
                __half2 h[8];
                h[0] = __floats2half2_rn(f0.x, f0.y); h[1] = __floats2half2_rn(f0.z, f0.w);
                h[2] = __floats2half2_rn(f1.x, f1.y); h[3] = __floats2half2_rn(f1.z, f1.w);
                h[4] = __floats2half2_rn(f2.x, f2.y); h[5] = __floats2half2_rn(f2.z, f2.w);
                h[6] = __floats2half2_rn(f3.x, f3.y); h[7] = __floats2half2_rn(f3.z, f3.w);
                *(uint4*)&g_h16[gr * 128 + cg + s * 16]     = *(uint4*)&h[0];
                *(uint4*)&g_h16[gr * 128 + cg + s * 16 + 8] = *(uint4*)&h[4];
            }
        }
    }
}

// ---------------- fused layer-1 GEMM + CSR fill ----------------
__global__ void k_l1(const float* __restrict__ x, const float* __restrict__ W1,
                     const int* __restrict__ src, const int* __restrict__ dst,
                     int n, int E, int gemmBlocks) {
    if ((int)blockIdx.x < gemmBlocks) {
        if (blockIdx.x == 0 && threadIdx.x < 128) {
            g_sum1[threadIdx.x] = 0.f; g_sq1[threadIdx.x] = 0.f;
            g_sum2[threadIdx.x] = 0.f; g_sq2[threadIdx.x] = 0.f;
        }
        gemm_body<false>(x, W1, n, blockIdx.x, nullptr, nullptr);
    } else {
        int e = ((int)blockIdx.x - gemmBlocks) * (int)blockDim.x + (int)threadIdx.x;
        if (e < E) {
            int d = dst[e];
            int p = atomicAdd(&g_cur[d], 1);
            g_col[p] = src[e];
        }
    }
}

__global__ void k_gemm2(const float* __restrict__ W2, const float* __restrict__ gma,
                        const float* __restrict__ bet, int n) {
    gemm_body<true>(g_agg, W2, n, blockIdx.x, gma, bet);
}

// ---------------- aggregation + fused BN stats (unchanged from r16) ----------------
template <int LAYER>
__global__ void k_agg_gather(int n) {
    __shared__ float s_val[8][128];
    __shared__ float s_sq [8][128];
    __shared__ int   s_idx[8][32];
    __shared__ float s_nrm[8][32];
    const int warp = threadIdx.x >> 5;
    const int lane = threadIdx.x & 31;
    const int node = blockIdx.x * 8 + warp;
    const int fofs = lane << 2;

    float4 acc0 = make_float4(0.f, 0.f, 0.f, 0.f);
    float4 acc1 = make_float4(0.f, 0.f, 0.f, 0.f);
    if (node < n) {
        const float dd = g_dis[node];
        const float dd2 = dd * dd;
        {
            uint2 raw = *(const uint2*)&g_h16[node * 128 + fofs];
            float2 f01 = __half22float2(*(__half2*)&raw.x);
            float2 f23 = __half22float2(*(__half2*)&raw.y);
            acc0.x = f01.x * dd2; acc0.y = f01.y * dd2;
            acc0.z = f23.x * dd2; acc0.w = f23.y * dd2;
        }

        const int beg = g_row[node];
        const int end = g_row[node + 1];
        for (int base = beg; base < end; base += 32) {
            int idx = base + lane;
            if (idx < end) {
                int s = g_col[idx];
                s_idx[warp][lane] = s;
                s_nrm[warp][lane] = g_dis[s] * dd;
            }
            __syncwarp();
            const int cnt = min(32, end - base);
            int k = 0;
            #pragma unroll 4
            for (; k + 2 <= cnt; k += 2) {
                int   sk0 = s_idx[warp][k];
                int   sk1 = s_idx[warp][k + 1];
                float nk0 = s_nrm[warp][k];
                float nk1 = s_nrm[warp][k + 1];
                uint2 r0 = *(const uint2*)&g_h16[sk0 * 128 + fofs];
                uint2 r1 = *(const uint2*)&g_h16[sk1 * 128 + fofs];
                float2 a01 = __half22float2(*(__half2*)&r0.x);
                float2 a23 = __half22float2(*(__half2*)&r0.y);
                float2 b01 = __half22float2(*(__half2*)&r1.x);
                float2 b23 = __half22float2(*(__half2*)&r1.y);
                acc0.x += a01.x * nk0; acc0.y += a01.y * nk0;
                acc0.z += a23.x * nk0; acc0.w += a23.y * nk0;
                acc1.x += b01.x * nk1; acc1.y += b01.y * nk1;
                acc1.z += b23.x * nk1; acc1.w += b23.y * nk1;
            }
            if (k < cnt) {
                int   sk = s_idx[warp][k];
                float nk = s_nrm[warp][k];
                uint2 r0 = *(const uint2*)&g_h16[sk * 128 + fofs];
                float2 a01 = __half22float2(*(__half2*)&r0.x);
                float2 a23 = __half22float2(*(__half2*)&r0.y);
                acc0.x += a01.x * nk; acc0.y += a01.y * nk;
                acc0.z += a23.x * nk; acc0.w += a23.y * nk;
            }
            __syncwarp();
        }
        acc0.x += acc1.x; acc0.y += acc1.y; acc0.z += acc1.z; acc0.w += acc1.w;
        *(float4*)&g_agg[node * 128 + fofs] = acc0;
    }

    *(float4*)&s_val[warp][fofs] = acc0;
    *(float4*)&s_sq [warp][fofs] =
        make_float4(acc0.x * acc0.x, acc0.y * acc0.y, acc0.z * acc0.z, acc0.w * acc0.w);
    __syncthreads();

    const int c    = threadIdx.x & 127;
    const int half = threadIdx.x >> 7;
    float tot = 0.f;
    #pragma unroll
    for (int w = 0; w < 8; w++) tot += half ? s_sq[w][c] : s_val[w][c];
    float* dest = (LAYER == 1) ? (half ? g_sq1 : g_sum1) : (half ? g_sq2 : g_sum2);
    atomicAdd(&dest[c], tot);
}

// ---------------- pooling with inline layer-2 BN+ReLU (batch sorted) ----------------
__global__ void k_pool(const int* __restrict__ batch, const float* __restrict__ gma,
                       const float* __restrict__ bet, int n) {
    const int c = threadIdx.x;
    float inv_n = 1.0f / (float)n;
    float mu  = g_sum2[c] * inv_n;
    float var = g_sq2[c] * inv_n - mu * mu;
    float scale = gma[c] * rsqrtf(var + BN_EPS);
    float shift = bet[c] - mu * scale;

    const int chunk = (n + gridDim.x - 1) / gridDim.x;
    const int i0 = blockIdx.x * chunk;
    const int i1 = min(n, i0 + chunk);
    if (i0 >= i1) return;

    int curg = batch[i0];
    float acc = 0.f, cacc = 0.f;
    for (int i = i0; i < i1; i++) {
        int g = batch[i];
        if (g != curg) {
            atomicAdd(&g_pool[curg * 128 + c], acc);
            if (c == 0) atomicAdd(&g_cnt[curg], cacc);
            acc = 0.f; cacc = 0.f; curg = g;
        }
        acc += fmaxf(fmaf(g_agg[i * 128 + c], scale, shift), 0.f);
        cacc += 1.f;
    }
    atomicAdd(&g_pool[curg * 128 + c], acc);
    if (c == 0) atomicAdd(&g_cnt[curg], cacc);
}

// ---------------- output + tail-zero ----------------
__global__ void k_out(const float* __restrict__ Wout, const float* __restrict__ bout,
                      float* __restrict__ out) {
    __shared__ float p[128];
    const int g = blockIdx.x;
    const int t = threadIdx.x;
    float c = fmaxf(g_cnt[g], 1.0f);
    p[t] = g_pool[g * 128 + t] / c;
    __syncthreads();

    g_pool[g * 128 + t] = 0.f;
    if (t == 0) g_cnt[g] = 0.f;
    for (int i = g * 128 + t; i < NMAX; i += GNUM * 128) g_degi[i] = 0;

    if (t < ODIM) {
        float s = bout[t];
        #pragma unroll 16
        for (int f = 0; f < 128; f++) s += p[f] * Wout[f * ODIM + t];
        out[g * ODIM + t] = s;
    }
}

// ---------------- launch ----------------
extern "C" void kernel_launch(void* const* d_in, const int* in_sizes, int n_in,
                              void* d_out, int out_size) {
    const float* x     = (const float*)d_in[0];
    const int*   ei    = (const int*)d_in[1];     // int32 (JAX default int)
    const int*   batch = (const int*)d_in[2];
    const float* W1    = (const float*)d_in[3];
    const float* g1    = (const float*)d_in[5];
    const float* be1   = (const float*)d_in[6];
    const float* W2    = (const float*)d_in[7];
    const float* g2    = (const float*)d_in[9];
    const float* be2   = (const float*)d_in[10];
    const float* Wout  = (const float*)d_in[11];
    const float* bout  = (const float*)d_in[12];
    float*       out   = (float*)d_out;

    const int n = in_sizes[0] / HDIM;
    const int E = in_sizes[1] / 2;
    const int* src = ei;
    const int* dst = ei + E;

    const int TB = 256;
    const int edgeBlocks     = (E + TB - 1) / TB;
    const int nodeWarpBlocks = (n + 7) / 8;
    const int gemmBlocks     = (n + 63) / 64;

    k_deg_count<<<edgeBlocks, TB>>>(dst, E);
    k_scan<<<1, 1024>>>(n);
    k_l1<<<gemmBlocks + edgeBlocks, TB>>>(x, W1, src, dst, n, E, gemmBlocks);
    k_agg_gather<1><<<nodeWarpBlocks, TB>>>(n);       // <- profiled slot
    k_gemm2<<<gemmBlocks, TB>>>(W2, g1, be1, n);
    k_agg_gather<2><<<nodeWarpBlocks, TB>>>(n);
    k_pool<<<512, 128>>>(batch, g2, be2, n);
    k_out<<<GNUM, 128>>>(Wout, bout, out);
}